// round 6
// baseline (speedup 1.0000x reference)
#include <cuda_runtime.h>
#include <cstddef>
#include <cstdint>

// Problem constants (match reference)
#define BB 4
#define CC 256
#define HH 512
#define WW 512
#define NROIS 32
#define OUT 7
#define TS 68   // smem tile row stride in floats (16B-aligned)

__device__ int4 g_boxes[NROIS];

__device__ __forceinline__ void cp_async16(uint32_t smem_dst, const void* gmem_src) {
    asm volatile("cp.async.cg.shared.global [%0], [%1], 16;\n"
                 :: "r"(smem_dst), "l"(gmem_src));
}
__device__ __forceinline__ void cp_async_commit_wait() {
    asm volatile("cp.async.commit_group;\n"
                 "cp.async.wait_group 0;\n" ::: "memory");
}

// Decode ROI boxes once (handles int64-vs-int32 harness dtype ambiguity).
__global__ void decode_rois_kernel(const void* __restrict__ rois_raw) {
    int t = threadIdx.x;   // 0..31
    const long long* r64 = (const long long*)rois_raw;
    const int*       r32 = (const int*)rois_raw;
    long long p0 = r64[0], p1 = r64[1], p2 = r64[2], p3 = r64[3];
    bool is64 = (p0 >= 0 && p0 <= WW) && (p1 >= 0 && p1 <= HH) &&
                (p2 > p0 && p2 <= WW) && (p3 > p1 && p3 <= HH);
    int4 box;
    if (is64) {
        box = make_int4((int)r64[t * 4 + 0], (int)r64[t * 4 + 1],
                        (int)r64[t * 4 + 2], (int)r64[t * 4 + 3]);
    } else {
        box = make_int4(r32[t * 4 + 0], r32[t * 4 + 1],
                        r32[t * 4 + 2], r32[t * 4 + 3]);
    }
    g_boxes[t] = box;
}

// One CTA per (roi, b, c), 256 threads.
// Phase 1: half-warp-per-row staging via 16B cp.async.cg (16 rows per iter).
// Phase 2: 2 threads per output bin (parity rows) + shfl combine.
__global__ __launch_bounds__(256)
void roi_adaptive_pool_kernel(const float* __restrict__ x,
                              float* __restrict__ out)
{
    int bid = blockIdx.x;
    int c   = bid & (CC - 1);
    int t   = bid >> 8;           // / CC
    int b   = t & (BB - 1);
    int roi = t >> 2;             // / BB

    int4 box = g_boxes[roi];
    int x1 = box.x, y1 = box.y, x2 = box.z, y2 = box.w;

    int w = x2 - x1;                   // 16..63
    int h = y2 - y1;                   // 16..63
    int xa = x1 & ~3;                  // 16B-aligned row start
    int ox = x1 - xa;                  // 0..3
    int nc = (x2 - xa + 3) >> 2;       // float4 chunks per row (4..17)

    __shared__ float tile[64 * TS];    // 17408 B

    const float* plane = x + ((size_t)(b * CC + c)) * (HH * WW);

    // Phase 1: 16 half-warps; half-warp hw covers rows hw, hw+16, ...
    {
        int lane16 = threadIdx.x & 15;
        int hw     = threadIdx.x >> 4;     // 0..15
        uint32_t sbase = (uint32_t)__cvta_generic_to_shared(tile);
        const char* gp = (const char*)(plane + (size_t)(y1 + hw) * WW + xa)
                         + lane16 * 16;
        uint32_t dp = sbase + (uint32_t)(hw * TS + lane16 * 4) * 4u;
        bool doA = lane16 < nc;
        bool doB = (nc > 16) && (lane16 == 0);   // rare chunk 16
        for (int rr = hw; rr < h; rr += 16) {
            if (doA) cp_async16(dp, gp);
            if (doB) cp_async16(dp + 256u, gp + 256);
            gp += 16 * WW * 4;
            dp += 16u * TS * 4u;
        }
    }
    cp_async_commit_wait();
    __syncthreads();

    // Phase 2: threads 0..127 all participate (converged shfl); 2 per bin.
    int tb = threadIdx.x;
    if (tb < 128) {
        int bin = tb >> 1;
        if (bin > 48) bin = 48;        // clamp so warp 3 stays converged
        int p = tb & 1;
        int i = bin / 7;
        int j = bin - i * 7;
        int hs = (i * h) / OUT;
        int he = ((i + 1) * h + OUT - 1) / OUT;
        int ws = (j * w) / OUT;
        int we = ((j + 1) * w + OUT - 1) / OUT;
        int ncol = we - ws;

        float s = 0.0f;
        const float* row = tile + (hs + p) * TS + ox + ws;
        for (int rr = hs + p; rr < he; rr += 2) {
            #pragma unroll 4
            for (int cc = 0; cc < ncol; ++cc)
                s += row[cc];
            row += 2 * TS;
        }
        s += __shfl_xor_sync(0xffffffffu, s, 1);

        if (p == 0 && tb < 2 * OUT * OUT) {
            float area = (float)((he - hs) * ncol);
            size_t oidx = ((((size_t)b * (NROIS * CC)) + (size_t)roi * CC + c)
                           * (OUT * OUT)) + bin;
            out[oidx] = s / area;
        }
    }
}

extern "C" void kernel_launch(void* const* d_in, const int* in_sizes, int n_in,
                              void* d_out, int out_size)
{
    const float* x    = (const float*)d_in[0];
    const void*  rois = d_in[1];
    float*       out  = (float*)d_out;

    decode_rois_kernel<<<1, NROIS>>>(rois);
    roi_adaptive_pool_kernel<<<NROIS * BB * CC, 256>>>(x, out);
}

// round 7
// speedup vs baseline: 1.0776x; 1.0776x over previous
#include <cuda_runtime.h>
#include <cstddef>
#include <cstdint>

// Problem constants (match reference)
#define BB 4
#define CC 256
#define HH 512
#define WW 512
#define NROIS 32
#define OUT 7
#define TS 68   // smem tile row stride in floats (16B-aligned)

__device__ int4 g_boxes[NROIS];

__device__ __forceinline__ void cp_async16(uint32_t smem_dst, const void* gmem_src) {
    asm volatile("cp.async.cg.shared.global [%0], [%1], 16;\n"
                 :: "r"(smem_dst), "l"(gmem_src));
}
__device__ __forceinline__ void cp_async_commit_wait() {
    asm volatile("cp.async.commit_group;\n"
                 "cp.async.wait_group 0;\n" ::: "memory");
}

// Decode ROI boxes once (handles int64-vs-int32 harness dtype ambiguity).
__global__ void decode_rois_kernel(const void* __restrict__ rois_raw) {
    int t = threadIdx.x;   // 0..31
    const long long* r64 = (const long long*)rois_raw;
    const int*       r32 = (const int*)rois_raw;
    long long p0 = r64[0], p1 = r64[1], p2 = r64[2], p3 = r64[3];
    bool is64 = (p0 >= 0 && p0 <= WW) && (p1 >= 0 && p1 <= HH) &&
                (p2 > p0 && p2 <= WW) && (p3 > p1 && p3 <= HH);
    int4 box;
    if (is64) {
        box = make_int4((int)r64[t * 4 + 0], (int)r64[t * 4 + 1],
                        (int)r64[t * 4 + 2], (int)r64[t * 4 + 3]);
    } else {
        box = make_int4(r32[t * 4 + 0], r32[t * 4 + 1],
                        r32[t * 4 + 2], r32[t * 4 + 3]);
    }
    g_boxes[t] = box;
}

// One CTA per (roi, b, c), 128 threads.
// Phase 1: warp per ROW PAIR (all 32 lanes issue cp.async) -> ceil(h/8) iters.
// Phase 2: 2 threads per output bin (parity rows) + shfl combine.
__global__ __launch_bounds__(128)
void roi_adaptive_pool_kernel(const float* __restrict__ x,
                              float* __restrict__ out)
{
    int bid = blockIdx.x;
    int c   = bid & (CC - 1);
    int t   = bid >> 8;           // / CC
    int b   = t & (BB - 1);
    int roi = t >> 2;             // / BB

    int4 box = g_boxes[roi];
    int x1 = box.x, y1 = box.y, x2 = box.z, y2 = box.w;

    int w = x2 - x1;                   // 16..63
    int h = y2 - y1;                   // 16..63
    int xa = x1 & ~3;                  // 16B-aligned row start
    int ox = x1 - xa;                  // 0..3
    int nc = (x2 - xa + 3) >> 2;       // float4 chunks per row (4..17)

    __shared__ float tile[64 * TS];    // 17408 B

    const float* plane = x + ((size_t)(b * CC + c)) * (HH * WW);

    // Phase 1: warp covers row pair (r0, r0+1); lane<16 -> r0, lane>=16 -> r0+1.
    {
        int lane  = threadIdx.x & 31;
        int warp  = threadIdx.x >> 5;
        int laneA = lane & 15;           // chunk index
        int half  = lane >> 4;           // which row of the pair
        int ncm   = nc < 16 ? nc : 16;
        bool doA  = laneA < ncm;
        bool doX  = (nc > 16) && (laneA == 15);   // rare 17th chunk (~6% of ROIs)

        uint32_t sbase = (uint32_t)__cvta_generic_to_shared(tile);
        int r = 2 * warp + half;
        const char* gp = (const char*)(plane + (size_t)(y1 + r) * WW + xa)
                         + laneA * 16;
        uint32_t dp = sbase + (uint32_t)(r * TS + laneA * 4) * 4u;
        for (; r < h; r += 8) {
            if (doA) cp_async16(dp, gp);
            if (doX) cp_async16(dp + 16u, gp + 16);
            gp += 8 * WW * 4;
            dp += 8u * TS * 4u;
        }
    }
    cp_async_commit_wait();
    __syncthreads();

    // Phase 2: all 128 threads participate (converged shfl); 2 per bin.
    {
        int tb  = threadIdx.x;
        int bin = tb >> 1;
        if (bin > 48) bin = 48;        // keep warp 3 converged
        int p = tb & 1;
        int i = bin / 7;
        int j = bin - i * 7;
        int hs = (i * h) / OUT;
        int he = ((i + 1) * h + OUT - 1) / OUT;
        int ws = (j * w) / OUT;
        int we = ((j + 1) * w + OUT - 1) / OUT;
        int ncol = we - ws;

        float s = 0.0f;
        const float* row = tile + (hs + p) * TS + ox + ws;
        for (int rr = hs + p; rr < he; rr += 2) {
            #pragma unroll 4
            for (int cc = 0; cc < ncol; ++cc)
                s += row[cc];
            row += 2 * TS;
        }
        s += __shfl_xor_sync(0xffffffffu, s, 1);

        if (p == 0 && tb < 2 * OUT * OUT) {
            float area = (float)((he - hs) * ncol);
            size_t oidx = ((((size_t)b * (NROIS * CC)) + (size_t)roi * CC + c)
                           * (OUT * OUT)) + bin;
            out[oidx] = s / area;
        }
    }
}

extern "C" void kernel_launch(void* const* d_in, const int* in_sizes, int n_in,
                              void* d_out, int out_size)
{
    const float* x    = (const float*)d_in[0];
    const void*  rois = d_in[1];
    float*       out  = (float*)d_out;

    decode_rois_kernel<<<1, NROIS>>>(rois);
    roi_adaptive_pool_kernel<<<NROIS * BB * CC, 128>>>(x, out);
}